// round 12
// baseline (speedup 1.0000x reference)
#include <cuda_runtime.h>

// Problem constants
#define Bb 512
#define Ss 1024
#define Ff 64
#define Ll 128
#define Gg 512    // 4*L
#define BT 4      // batch rows per CTA
#define CRg 88    // W cols per gate in registers (44 f32x2 k-pairs)
#define NWC 10    // W smem float4 chunks per gate (40 cols)
#define HBUF 132  // float4 stride of one h buffer (128 used + 4 pad)

typedef unsigned long long ull;

// ------------------------- device scratch -------------------------
__device__ float g_gx[(size_t)Bb * Ss * Gg];    // x-proj + enc bias, natural [row][gate] (1 GB)
__device__ float g_hall[(size_t)Bb * Ss * Ll];  // decoder h states (256 MB)
__device__ float g_weff[Gg * Ll];               // W_hh_dec + W_ih_dec @ W_dense
__device__ float g_benc[Gg];
__device__ float g_beff[Gg];
__device__ float g_hn[Bb * Ll];
__device__ float g_cn[Bb * Ll];

// ------------------------- helpers -------------------------
__device__ __forceinline__ ull pk(float x, float y) {
    ull r; asm("mov.b64 %0, {%1, %2};" : "=l"(r) : "f"(x), "f"(y)); return r;
}
__device__ __forceinline__ void upk(ull v, float& x, float& y) {
    asm("mov.b64 {%0, %1}, %2;" : "=f"(x), "=f"(y) : "l"(v));
}
__device__ __forceinline__ void fma2(ull& d, ull a, ull b) {
    asm("fma.rn.f32x2 %0, %1, %2, %0;" : "+l"(d) : "l"(a), "l"(b));
}
__device__ __forceinline__ float ex2a(float x) {
    float r; asm("ex2.approx.f32 %0, %1;" : "=f"(r) : "f"(x)); return r;
}
__device__ __forceinline__ float rcpa(float x) {
    float r; asm("rcp.approx.f32 %0, %1;" : "=f"(r) : "f"(x)); return r;
}
__device__ __forceinline__ float fsig(float x) {
    return rcpa(1.0f + ex2a(-1.4426950408889634f * x));
}
__device__ __forceinline__ float ftanh(float x) {
    return fmaf(2.0f, rcpa(1.0f + ex2a(-2.8853900817779268f * x)), -1.0f);
}

// h buffer float index for value h[k][r] (interleaved for broadcast pair loads):
// float4 slot (k>>1)*2 + (r>>1) holds {h[2k2][r0], h[2k2+1][r0], h[2k2][r0+1], h[2k2+1][r0+1]}
__device__ __forceinline__ int hidx(int k, int r) {
    return ((k >> 1) * 2 + (r >> 1)) * 4 + (r & 1) * 2 + (k & 1);
}

// ------------------------- setup: fold decoder matrices -------------------------
__global__ void setup_kernel(const float* __restrict__ Wih_d,
                             const float* __restrict__ Whh_d,
                             const float* __restrict__ bih_d,
                             const float* __restrict__ bhh_d,
                             const float* __restrict__ Wdn,
                             const float* __restrict__ bdn,
                             const float* __restrict__ bih_e,
                             const float* __restrict__ bhh_e) {
    int j = blockIdx.x;   // gate 0..511
    int k = threadIdx.x;  // latent 0..127
    float s = 0.0f;
    for (int m = 0; m < Ff; m++) s += Wih_d[j * Ff + m] * Wdn[m * Ll + k];
    g_weff[j * Ll + k] = Whh_d[j * Ll + k] + s;
    if (k == 0) {
        float bs = bih_d[j] + bhh_d[j];
        for (int m = 0; m < Ff; m++) bs += Wih_d[j * Ff + m] * bdn[m];
        g_beff[j] = bs;
        g_benc[j] = bih_e[j] + bhh_e[j];
    }
}

// ------------------------- x-projection GEMM -------------------------
// gx[row][j] = b_enc[j] + x[row,:] @ W_ih_enc[j,:]   (natural gate order)
__global__ void __launch_bounds__(256, 1)
xproj_kernel(const float* __restrict__ x, const float* __restrict__ Wih) {
    extern __shared__ char smraw[];
    ulonglong2* Wsm = (ulonglong2*)smraw;            // [16][512] float4 = 128KB
    float* xs = (float*)(smraw + 16 * 512 * 16);     // [32][64] = 8KB
    const int t_ = threadIdx.x;
    const int gA = t_, gB = t_ + 256;

    const float4* wa = (const float4*)(Wih + gA * Ff);
    const float4* wb = (const float4*)(Wih + gB * Ff);
#pragma unroll
    for (int kg = 0; kg < 16; kg++) {
        ((float4*)Wsm)[kg * 512 + gA] = wa[kg];
        ((float4*)Wsm)[kg * 512 + gB] = wb[kg];
    }
    const float bA = g_benc[gA], bB = g_benc[gB];
    const size_t row0 = (size_t)blockIdx.x * 32;

    ((float4*)xs)[t_]       = ((const float4*)x)[row0 * 16 + t_];
    ((float4*)xs)[t_ + 256] = ((const float4*)x)[row0 * 16 + t_ + 256];
    __syncthreads();

    ull aA[32], aB[32];
#pragma unroll
    for (int r = 0; r < 32; r++) { aA[r] = 0ull; aB[r] = 0ull; }

#pragma unroll 4
    for (int kg = 0; kg < 16; kg++) {
        ulonglong2 wAv = Wsm[kg * 512 + gA];
        ulonglong2 wBv = Wsm[kg * 512 + gB];
#pragma unroll
        for (int r = 0; r < 32; r++) {
            ulonglong2 hh = *(const ulonglong2*)(xs + r * Ff + 4 * kg);
            fma2(aA[r], hh.x, wAv.x); fma2(aA[r], hh.y, wAv.y);
            fma2(aB[r], hh.x, wBv.x); fma2(aB[r], hh.y, wBv.y);
        }
    }
#pragma unroll
    for (int r = 0; r < 32; r++) {
        float lo, hi;
        upk(aA[r], lo, hi); g_gx[(row0 + r) * Gg + gA] = lo + hi + bA;
        upk(aB[r], lo, hi); g_gx[(row0 + r) * Gg + gB] = lo + hi + bB;
    }
}

// ------------------------- recurrent kernels -------------------------
// 512 threads. Phase 1: thread j computes gate j for all 4 rows.
//   W row j: k<CRg in registers, rest from Wsm[ch][j] (lane-distinct, coalesced).
//   h read via WARP-UNIFORM broadcast LDS.128 from interleaved double buffer.
//   Accumulators are f32x2 over k-parity; gate value written to gs[r][j].
// Phase 2: thread (l = tid&127, r = tid>>7) does the cell update; c in register.
// Two barriers per step.

__global__ void __launch_bounds__(512, 1)
enc_kernel(const float* __restrict__ Whh) {
    extern __shared__ char smraw[];
    float4* Wsm = (float4*)smraw;                            // NWC*512 float4 = 80KB
    float4* hf4 = (float4*)(smraw + NWC * 512 * 16);         // [2][HBUF] float4
    float* gs = (float*)(smraw + NWC * 512 * 16 + 2 * HBUF * 16);  // [4][512]
    const int j = threadIdx.x;
    const int l = j & 127, r = j >> 7;
    const int b0 = blockIdx.x * BT;

    ull Wr[CRg / 2];
    {
        const float4* wrow = (const float4*)(Whh + j * Ll);
#pragma unroll
        for (int q = 0; q < CRg / 4; q++) {
            float4 v = wrow[q];
            Wr[2 * q] = pk(v.x, v.y); Wr[2 * q + 1] = pk(v.z, v.w);
        }
#pragma unroll
        for (int ch = 0; ch < NWC; ch++)
            Wsm[ch * 512 + j] = wrow[CRg / 4 + ch];
    }
    // zero h buffer 0 (thread (l,r) owns slot (k=l, r))
    ((float*)hf4)[hidx(l, r)] = 0.0f;
    float c = 0.0f, hn = 0.0f;
    __syncthreads();

    for (int t = 0; t < Ss; t++) {
        float gxv[BT];
#pragma unroll
        for (int rr = 0; rr < BT; rr++)
            gxv[rr] = g_gx[((size_t)(b0 + rr) * Ss + t) * Gg + j];
        const float4* hb = hf4 + (t & 1) * HBUF;
        ull a0 = 0, a1 = 0, a2 = 0, a3 = 0;
        // register W part: k-pairs 0..CRg/2
#pragma unroll
        for (int k2 = 0; k2 < CRg / 2; k2++) {
            ulonglong2 h01 = *(const ulonglong2*)(hb + 2 * k2);      // rows 0,1
            ulonglong2 h23 = *(const ulonglong2*)(hb + 2 * k2 + 1);  // rows 2,3
            fma2(a0, h01.x, Wr[k2]); fma2(a1, h01.y, Wr[k2]);
            fma2(a2, h23.x, Wr[k2]); fma2(a3, h23.y, Wr[k2]);
        }
        // smem W part: NWC chunks of 2 k-pairs
#pragma unroll
        for (int ch = 0; ch < NWC; ch++) {
            ulonglong2 wv = *(const ulonglong2*)(Wsm + ch * 512 + j);
            int k2 = CRg / 2 + 2 * ch;
            ulonglong2 h01 = *(const ulonglong2*)(hb + 2 * k2);
            ulonglong2 h23 = *(const ulonglong2*)(hb + 2 * k2 + 1);
            fma2(a0, h01.x, wv.x); fma2(a1, h01.y, wv.x);
            fma2(a2, h23.x, wv.x); fma2(a3, h23.y, wv.x);
            h01 = *(const ulonglong2*)(hb + 2 * k2 + 2);
            h23 = *(const ulonglong2*)(hb + 2 * k2 + 3);
            fma2(a0, h01.x, wv.y); fma2(a1, h01.y, wv.y);
            fma2(a2, h23.x, wv.y); fma2(a3, h23.y, wv.y);
        }
        float lo, hi;
        upk(a0, lo, hi); gs[0 * 512 + j] = lo + hi + gxv[0];
        upk(a1, lo, hi); gs[1 * 512 + j] = lo + hi + gxv[1];
        upk(a2, lo, hi); gs[2 * 512 + j] = lo + hi + gxv[2];
        upk(a3, lo, hi); gs[3 * 512 + j] = lo + hi + gxv[3];
        __syncthreads();
        // cell update for (l, r)
        {
            float vi = gs[r * 512 + l];
            float vf = gs[r * 512 + 128 + l];
            float vg = gs[r * 512 + 256 + l];
            float vo = gs[r * 512 + 384 + l];
            c = fsig(vf) * c + fsig(vi) * ftanh(vg);
            hn = fsig(vo) * ftanh(c);
            ((float*)(hf4 + ((t + 1) & 1) * HBUF))[hidx(l, r)] = hn;
        }
        __syncthreads();
    }
    g_hn[(b0 + r) * Ll + l] = hn;
    g_cn[(b0 + r) * Ll + l] = c;
}

__global__ void __launch_bounds__(512, 1)
dec_kernel() {
    extern __shared__ char smraw[];
    float4* Wsm = (float4*)smraw;
    float4* hf4 = (float4*)(smraw + NWC * 512 * 16);
    float* gs = (float*)(smraw + NWC * 512 * 16 + 2 * HBUF * 16);
    const int j = threadIdx.x;
    const int l = j & 127, r = j >> 7;
    const int b0 = blockIdx.x * BT;

    ull Wr[CRg / 2];
    {
        const float4* wrow = (const float4*)(g_weff + j * Ll);
#pragma unroll
        for (int q = 0; q < CRg / 4; q++) {
            float4 v = wrow[q];
            Wr[2 * q] = pk(v.x, v.y); Wr[2 * q + 1] = pk(v.z, v.w);
        }
#pragma unroll
        for (int ch = 0; ch < NWC; ch++)
            Wsm[ch * 512 + j] = wrow[CRg / 4 + ch];
    }
    const float be = g_beff[j];
    ((float*)hf4)[hidx(l, r)] = g_hn[(b0 + r) * Ll + l];
    float c = g_cn[(b0 + r) * Ll + l];
    float* hout = g_hall + ((size_t)(b0 + r) * Ss) * Ll + l;
    __syncthreads();

    for (int t = 0; t < Ss; t++) {
        const float4* hb = hf4 + (t & 1) * HBUF;
        ull a0 = 0, a1 = 0, a2 = 0, a3 = 0;
#pragma unroll
        for (int k2 = 0; k2 < CRg / 2; k2++) {
            ulonglong2 h01 = *(const ulonglong2*)(hb + 2 * k2);
            ulonglong2 h23 = *(const ulonglong2*)(hb + 2 * k2 + 1);
            fma2(a0, h01.x, Wr[k2]); fma2(a1, h01.y, Wr[k2]);
            fma2(a2, h23.x, Wr[k2]); fma2(a3, h23.y, Wr[k2]);
        }
#pragma unroll
        for (int ch = 0; ch < NWC; ch++) {
            ulonglong2 wv = *(const ulonglong2*)(Wsm + ch * 512 + j);
            int k2 = CRg / 2 + 2 * ch;
            ulonglong2 h01 = *(const ulonglong2*)(hb + 2 * k2);
            ulonglong2 h23 = *(const ulonglong2*)(hb + 2 * k2 + 1);
            fma2(a0, h01.x, wv.x); fma2(a1, h01.y, wv.x);
            fma2(a2, h23.x, wv.x); fma2(a3, h23.y, wv.x);
            h01 = *(const ulonglong2*)(hb + 2 * k2 + 2);
            h23 = *(const ulonglong2*)(hb + 2 * k2 + 3);
            fma2(a0, h01.x, wv.y); fma2(a1, h01.y, wv.y);
            fma2(a2, h23.x, wv.y); fma2(a3, h23.y, wv.y);
        }
        float lo, hi;
        upk(a0, lo, hi); gs[0 * 512 + j] = lo + hi + be;
        upk(a1, lo, hi); gs[1 * 512 + j] = lo + hi + be;
        upk(a2, lo, hi); gs[2 * 512 + j] = lo + hi + be;
        upk(a3, lo, hi); gs[3 * 512 + j] = lo + hi + be;
        __syncthreads();
        {
            float vi = gs[r * 512 + l];
            float vf = gs[r * 512 + 128 + l];
            float vg = gs[r * 512 + 256 + l];
            float vo = gs[r * 512 + 384 + l];
            c = fsig(vf) * c + fsig(vi) * ftanh(vg);
            float hn = fsig(vo) * ftanh(c);
            ((float*)(hf4 + ((t + 1) & 1) * HBUF))[hidx(l, r)] = hn;
            hout[(size_t)t * Ll] = hn;   // g_hall[b][t][l] = H_{t+1}, coalesced
        }
        __syncthreads();
    }
}

// ------------------------- output GEMM + flip -------------------------
__global__ void __launch_bounds__(256, 1)
out_kernel(const float* __restrict__ Wdn, const float* __restrict__ bdn,
           float* __restrict__ out) {
    extern __shared__ float hsm[];   // [128][128] = 64KB
    const int tid = threadIdx.x;
    const size_t row0 = (size_t)blockIdx.x * 128;
    for (int i = tid; i < 128 * Ll / 4; i += 256)
        ((float4*)hsm)[i] = ((const float4*)g_hall)[row0 * (Ll / 4) + i];

    const int f = tid & 63, rg = tid >> 6;
    ull Wd[64];
    const float4* wd = (const float4*)(Wdn + f * Ll);
#pragma unroll
    for (int q = 0; q < 32; q++) {
        float4 v = wd[q];
        Wd[2 * q] = pk(v.x, v.y); Wd[2 * q + 1] = pk(v.z, v.w);
    }
    const float bv = bdn[f];
    __syncthreads();

#pragma unroll 1
    for (int rr = 0; rr < 32; rr += 2) {
        int row = rg * 32 + rr;
        ull a0 = 0, a1 = 0;
#pragma unroll
        for (int q = 0; q < 32; q++) {
            ulonglong2 h0 = *(const ulonglong2*)(hsm + row * Ll + 4 * q);
            ulonglong2 h1 = *(const ulonglong2*)(hsm + (row + 1) * Ll + 4 * q);
            fma2(a0, h0.x, Wd[2 * q]); fma2(a0, h0.y, Wd[2 * q + 1]);
            fma2(a1, h1.x, Wd[2 * q]); fma2(a1, h1.y, Wd[2 * q + 1]);
        }
        float lo, hi;
        upk(a0, lo, hi); float s0 = lo + hi + bv;
        upk(a1, lo, hi); float s1 = lo + hi + bv;
        size_t g0 = row0 + row;
        size_t b_ = g0 >> 10; int t_ = (int)(g0 & 1023);
        out[(b_ * Ss + (size_t)(Ss - 1 - t_)) * Ff + f] = s0;
        g0 += 1;
        b_ = g0 >> 10; t_ = (int)(g0 & 1023);
        out[(b_ * Ss + (size_t)(Ss - 1 - t_)) * Ff + f] = s1;
    }
}

// ------------------------- launch -------------------------
extern "C" void kernel_launch(void* const* d_in, const int* in_sizes, int n_in,
                              void* d_out, int out_size) {
    const float* x     = (const float*)d_in[0];
    const float* Wih_e = (const float*)d_in[1];
    const float* Whh_e = (const float*)d_in[2];
    const float* bih_e = (const float*)d_in[3];
    const float* bhh_e = (const float*)d_in[4];
    const float* Wih_d = (const float*)d_in[5];
    const float* Whh_d = (const float*)d_in[6];
    const float* bih_d = (const float*)d_in[7];
    const float* bhh_d = (const float*)d_in[8];
    const float* Wdn   = (const float*)d_in[9];
    const float* bdn   = (const float*)d_in[10];
    float* out = (float*)d_out;

    const int SM_X = 16 * 512 * 16 + 32 * 64 * 4;                 // 139264
    const int SM_R = NWC * 512 * 16 + 2 * HBUF * 16 + 4 * 512 * 4; // 81920+4224+8192 = 94336
    const int SM_O = 128 * Ll * 4;                                // 65536

    cudaFuncSetAttribute(xproj_kernel, cudaFuncAttributeMaxDynamicSharedMemorySize, SM_X);
    cudaFuncSetAttribute(enc_kernel,   cudaFuncAttributeMaxDynamicSharedMemorySize, SM_R);
    cudaFuncSetAttribute(dec_kernel,   cudaFuncAttributeMaxDynamicSharedMemorySize, SM_R);
    cudaFuncSetAttribute(out_kernel,   cudaFuncAttributeMaxDynamicSharedMemorySize, SM_O);

    setup_kernel<<<Gg, Ll>>>(Wih_d, Whh_d, bih_d, bhh_d, Wdn, bdn, bih_e, bhh_e);
    xproj_kernel<<<(Bb * Ss) / 32, 256, SM_X>>>(x, Wih_e);
    enc_kernel<<<Bb / BT, 512, SM_R>>>(Whh_e);
    dec_kernel<<<Bb / BT, 512, SM_R>>>();
    out_kernel<<<(Bb * Ss) / 128, 256, SM_O>>>(Wdn, bdn, out);
}

// round 14
// speedup vs baseline: 1.3885x; 1.3885x over previous
#include <cuda_runtime.h>
#include <cuda_bf16.h>
#include <cstdint>
#include <cstring>

typedef unsigned long long ull;

#define Bb 512
#define Ss 1024
#define Ff 64
#define Ll 128
#define Gg 512

// recurrent smem layout (bytes)
#define WB   0                    // W staging / W_lo: 512 rows x 272B
#define HHI  139264               // h_hi B tile: 8 rows x 272B
#define HLO  (139264 + 2176)      // h_lo B tile
#define GSB  (139264 + 4352)      // gs: 512 gates x 10 floats
#define SMR  (GSB + 512 * 10 * 4) // 164096

__device__ float g_gx[(size_t)Bb * Ss * Gg];
__device__ float g_hall[(size_t)Bb * Ss * Ll];
__device__ float g_weff[Gg * Ll];
__device__ float g_benc[Gg];
__device__ float g_beff[Gg];
__device__ float g_hn[Bb * Ll];
__device__ float g_cn[Bb * Ll];

__device__ __forceinline__ ull pk(float x, float y) {
    ull r; asm("mov.b64 %0, {%1, %2};" : "=l"(r) : "f"(x), "f"(y)); return r;
}
__device__ __forceinline__ void upk(ull v, float& x, float& y) {
    asm("mov.b64 {%0, %1}, %2;" : "=f"(x), "=f"(y) : "l"(v));
}
__device__ __forceinline__ void fma2(ull& d, ull a, ull b) {
    asm("fma.rn.f32x2 %0, %1, %2, %0;" : "+l"(d) : "l"(a), "l"(b));
}
__device__ __forceinline__ float ex2a(float x) {
    float r; asm("ex2.approx.f32 %0, %1;" : "=f"(r) : "f"(x)); return r;
}
__device__ __forceinline__ float rcpa(float x) {
    float r; asm("rcp.approx.f32 %0, %1;" : "=f"(r) : "f"(x)); return r;
}
__device__ __forceinline__ float fsig(float x) {
    return rcpa(1.0f + ex2a(-1.4426950408889634f * x));
}
__device__ __forceinline__ float ftanh(float x) {
    return fmaf(2.0f, rcpa(1.0f + ex2a(-2.8853900817779268f * x)), -1.0f);
}
__device__ __forceinline__ uint32_t smem_u32(const void* p) {
    uint32_t a;
    asm("{ .reg .u64 t; cvta.to.shared.u64 t, %1; cvt.u32.u64 %0, t; }" : "=r"(a) : "l"(p));
    return a;
}
__device__ __forceinline__ void ldsm4(uint32_t* f, uint32_t a) {
    asm volatile("ldmatrix.sync.aligned.m8n8.x4.shared.b16 {%0,%1,%2,%3}, [%4];"
                 : "=r"(f[0]), "=r"(f[1]), "=r"(f[2]), "=r"(f[3]) : "r"(a));
}
__device__ __forceinline__ void ldsm2(uint32_t* f, uint32_t a) {
    asm volatile("ldmatrix.sync.aligned.m8n8.x2.shared.b16 {%0,%1}, [%2];"
                 : "=r"(f[0]), "=r"(f[1]) : "r"(a));
}
__device__ __forceinline__ void mma_bf16(float* d, const uint32_t* a, const uint32_t* b) {
    asm volatile("mma.sync.aligned.m16n8k16.row.col.f32.bf16.bf16.f32 "
                 "{%0,%1,%2,%3},{%4,%5,%6,%7},{%8,%9},{%0,%1,%2,%3};"
                 : "+f"(d[0]), "+f"(d[1]), "+f"(d[2]), "+f"(d[3])
                 : "r"(a[0]), "r"(a[1]), "r"(a[2]), "r"(a[3]), "r"(b[0]), "r"(b[1]));
}
__device__ __forceinline__ uint32_t pack_bf16(float a, float b) {
    __nv_bfloat16 x = __float2bfloat16(a), y = __float2bfloat16(b);
    uint16_t u0, u1; memcpy(&u0, &x, 2); memcpy(&u1, &y, 2);
    return (uint32_t)u0 | ((uint32_t)u1 << 16);
}

// ------------------------- setup -------------------------
__global__ void setup_kernel(const float* __restrict__ Wih_d, const float* __restrict__ Whh_d,
                             const float* __restrict__ bih_d, const float* __restrict__ bhh_d,
                             const float* __restrict__ Wdn, const float* __restrict__ bdn,
                             const float* __restrict__ bih_e, const float* __restrict__ bhh_e) {
    int j = blockIdx.x, k = threadIdx.x;
    float s = 0.0f;
    for (int m = 0; m < Ff; m++) s += Wih_d[j * Ff + m] * Wdn[m * Ll + k];
    g_weff[j * Ll + k] = Whh_d[j * Ll + k] + s;
    if (k == 0) {
        float bs = bih_d[j] + bhh_d[j];
        for (int m = 0; m < Ff; m++) bs += Wih_d[j * Ff + m] * bdn[m];
        g_beff[j] = bs;
        g_benc[j] = bih_e[j] + bhh_e[j];
    }
}

// ------------------------- x-projection (fp32 scalar, proven) -------------------------
__global__ void __launch_bounds__(256, 1)
xproj_kernel(const float* __restrict__ x, const float* __restrict__ Wih) {
    extern __shared__ char smraw[];
    ulonglong2* Wsm = (ulonglong2*)smraw;
    float* xs = (float*)(smraw + 16 * 512 * 16);
    const int t_ = threadIdx.x;
    const int gA = t_, gB = t_ + 256;
    const float4* wa = (const float4*)(Wih + gA * Ff);
    const float4* wb = (const float4*)(Wih + gB * Ff);
#pragma unroll
    for (int kg = 0; kg < 16; kg++) {
        ((float4*)Wsm)[kg * 512 + gA] = wa[kg];
        ((float4*)Wsm)[kg * 512 + gB] = wb[kg];
    }
    const float bA = g_benc[gA], bB = g_benc[gB];
    const size_t row0 = (size_t)blockIdx.x * 32;
    ((float4*)xs)[t_] = ((const float4*)x)[row0 * 16 + t_];
    ((float4*)xs)[t_ + 256] = ((const float4*)x)[row0 * 16 + t_ + 256];
    __syncthreads();
    ull aA[32], aB[32];
#pragma unroll
    for (int r = 0; r < 32; r++) { aA[r] = 0ull; aB[r] = 0ull; }
#pragma unroll 4
    for (int kg = 0; kg < 16; kg++) {
        ulonglong2 wAv = Wsm[kg * 512 + gA];
        ulonglong2 wBv = Wsm[kg * 512 + gB];
#pragma unroll
        for (int r = 0; r < 32; r++) {
            ulonglong2 hh = *(const ulonglong2*)(xs + r * Ff + 4 * kg);
            fma2(aA[r], hh.x, wAv.x); fma2(aA[r], hh.y, wAv.y);
            fma2(aB[r], hh.x, wBv.x); fma2(aB[r], hh.y, wBv.y);
        }
    }
#pragma unroll
    for (int r = 0; r < 32; r++) {
        float lo, hi;
        upk(aA[r], lo, hi); g_gx[(row0 + r) * Gg + gA] = lo + hi + bA;
        upk(aB[r], lo, hi); g_gx[(row0 + r) * Gg + gB] = lo + hi + bB;
    }
}

// ------------------------- recurrent: mma.sync bf16 hi/lo (4 terms) -------------------------
// 128 CTAs x 512 threads; 4 real rows (cols 0-3), N padded to 8 with zero rows.
// Warp w: gates [32w, 32w+32) = 2 m-tiles. W_hi A-frags resident in regs;
// W_lo in smem (ldmatrix per step); h as bf16 hi/lo B tiles [n][k], 272B stride.
// Cell update: thread (l = tid&127, r = tid>>7), c in register. 2 barriers/step.
template <bool ENC>
__global__ void __launch_bounds__(512, 1)
rec_kernel(const float* __restrict__ Wsrc) {
    extern __shared__ char sm[];
    const uint32_t smb = smem_u32(sm);
    const int tid = threadIdx.x;
    const int lane = tid & 31, w = tid >> 5;
    const int l = tid & 127, r = tid >> 7;
    const int b0 = blockIdx.x * 4;
    const float* W = ENC ? Wsrc : (const float*)g_weff;

    // stage W_hi into WB (row stride 272B)
    for (int idx = tid; idx < 512 * 128; idx += 512) {
        int g = idx >> 7, k = idx & 127;
        *(__nv_bfloat16*)(sm + WB + g * 272 + 2 * k) = __float2bfloat16(W[g * 128 + k]);
    }
    __syncthreads();

    const uint32_t laneA = (uint32_t)((lane & 15) * 272 + (lane >> 4) * 16);
    const uint32_t laneB = (uint32_t)((lane & 7) * 272 + ((lane >> 3) & 1) * 16);

    // resident A_hi fragments
    uint32_t Ahi[2][8][4];
#pragma unroll
    for (int mt = 0; mt < 2; mt++) {
        uint32_t gb = smb + WB + (uint32_t)(w * 32 + mt * 16) * 272 + laneA;
#pragma unroll
        for (int kt = 0; kt < 8; kt++) ldsm4(Ahi[mt][kt], gb + kt * 32);
    }
    __syncthreads();

    // overwrite WB with W_lo residuals
    for (int idx = tid; idx < 512 * 128; idx += 512) {
        int g = idx >> 7, k = idx & 127;
        float wv = W[g * 128 + k];
        __nv_bfloat16 hh = __float2bfloat16(wv);
        *(__nv_bfloat16*)(sm + WB + g * 272 + 2 * k) =
            __float2bfloat16(wv - __bfloat162float(hh));
    }
    // zero h tiles (hi+lo = 4352B)
    for (int idx = tid; idx < 1088; idx += 512) ((uint32_t*)(sm + HHI))[idx] = 0u;

    float c, be0, be1, be2, be3, hn = 0.0f;
    if (ENC) {
        c = 0.0f;
    } else {
        c = g_cn[(b0 + r) * Ll + l];
        be0 = g_beff[l]; be1 = g_beff[128 + l]; be2 = g_beff[256 + l]; be3 = g_beff[384 + l];
    }
    __syncthreads();
    if (!ENC) {  // seed h from encoder
        float h0 = g_hn[(b0 + r) * Ll + l];
        float h1 = __shfl_down_sync(0xffffffffu, h0, 1);
        if (!(l & 1)) {
            __nv_bfloat16 a = __float2bfloat16(h0), b = __float2bfloat16(h1);
            *(uint32_t*)(sm + HHI + r * 272 + 2 * l) = pack_bf16(h0, h1);
            *(uint32_t*)(sm + HLO + r * 272 + 2 * l) =
                pack_bf16(h0 - __bfloat162float(a), h1 - __bfloat162float(b));
        }
        __syncthreads();
    }

    const uint32_t bhiB = smb + HHI + laneB;
    const uint32_t bloB = smb + HLO + laneB;
    float* gs = (float*)(sm + GSB);

    for (int t = 0; t < Ss; t++) {
        float gx0, gx1, gx2, gx3;
        if (ENC) {
            const float* p = g_gx + ((size_t)(b0 + r) * Ss + t) * Gg + l;
            gx0 = p[0]; gx1 = p[128]; gx2 = p[256]; gx3 = p[384];
        }
        // B fragments for this step
        uint32_t Bh[8][2], Bl[8][2];
#pragma unroll
        for (int kt = 0; kt < 8; kt++) {
            ldsm2(Bh[kt], bhiB + kt * 32);
            ldsm2(Bl[kt], bloB + kt * 32);
        }
        // GEMM: D = (Whi+Wlo)(hhi+hlo), fp32 accum
#pragma unroll
        for (int mt = 0; mt < 2; mt++) {
            float D[4] = {0.f, 0.f, 0.f, 0.f};
            uint32_t gb = smb + WB + (uint32_t)(w * 32 + mt * 16) * 272 + laneA;
#pragma unroll
            for (int kt = 0; kt < 8; kt++) {
                uint32_t Al[4];
                ldsm4(Al, gb + kt * 32);
                mma_bf16(D, Ahi[mt][kt], Bh[kt]);
                mma_bf16(D, Ahi[mt][kt], Bl[kt]);
                mma_bf16(D, Al, Bh[kt]);
                mma_bf16(D, Al, Bl[kt]);
            }
            int g0 = w * 32 + mt * 16 + (lane >> 2);
            int cc = (lane & 3) * 2;
            *(float2*)(gs + g0 * 10 + cc) = make_float2(D[0], D[1]);
            *(float2*)(gs + (g0 + 8) * 10 + cc) = make_float2(D[2], D[3]);
        }
        __syncthreads();
        // cell update for (l, r)
        {
            float vi = gs[l * 10 + r]         + (ENC ? gx0 : be0);
            float vf = gs[(128 + l) * 10 + r] + (ENC ? gx1 : be1);
            float vg = gs[(256 + l) * 10 + r] + (ENC ? gx2 : be2);
            float vo = gs[(384 + l) * 10 + r] + (ENC ? gx3 : be3);
            c = fsig(vf) * c + fsig(vi) * ftanh(vg);
            hn = fsig(vo) * ftanh(c);
            if (!ENC) g_hall[((size_t)(b0 + r) * Ss + t) * Ll + l] = hn;
            float hn1 = __shfl_down_sync(0xffffffffu, hn, 1);
            if (!(l & 1)) {
                __nv_bfloat16 a = __float2bfloat16(hn), b = __float2bfloat16(hn1);
                *(uint32_t*)(sm + HHI + r * 272 + 2 * l) = pack_bf16(hn, hn1);
                *(uint32_t*)(sm + HLO + r * 272 + 2 * l) =
                    pack_bf16(hn - __bfloat162float(a), hn1 - __bfloat162float(b));
            }
        }
        __syncthreads();
    }
    if (ENC) {
        g_hn[(b0 + r) * Ll + l] = hn;
        g_cn[(b0 + r) * Ll + l] = c;
    }
}

// ------------------------- output GEMM + flip (proven) -------------------------
__global__ void __launch_bounds__(256, 1)
out_kernel(const float* __restrict__ Wdn, const float* __restrict__ bdn,
           float* __restrict__ out) {
    extern __shared__ float hsm[];
    const int tid = threadIdx.x;
    const size_t row0 = (size_t)blockIdx.x * 128;
    for (int i = tid; i < 128 * Ll / 4; i += 256)
        ((float4*)hsm)[i] = ((const float4*)g_hall)[row0 * (Ll / 4) + i];
    const int f = tid & 63, rgq = tid >> 6;
    ull Wd[64];
    const float4* wd = (const float4*)(Wdn + f * Ll);
#pragma unroll
    for (int q = 0; q < 32; q++) {
        float4 v = wd[q];
        Wd[2 * q] = pk(v.x, v.y); Wd[2 * q + 1] = pk(v.z, v.w);
    }
    const float bv = bdn[f];
    __syncthreads();
#pragma unroll 1
    for (int rr = 0; rr < 32; rr += 2) {
        int row = rgq * 32 + rr;
        ull a0 = 0, a1 = 0;
#pragma unroll
        for (int q = 0; q < 32; q++) {
            ulonglong2 h0 = *(const ulonglong2*)(hsm + row * Ll + 4 * q);
            ulonglong2 h1 = *(const ulonglong2*)(hsm + (row + 1) * Ll + 4 * q);
            fma2(a0, h0.x, Wd[2 * q]); fma2(a0, h0.y, Wd[2 * q + 1]);
            fma2(a1, h1.x, Wd[2 * q]); fma2(a1, h1.y, Wd[2 * q + 1]);
        }
        float lo, hi;
        upk(a0, lo, hi); float s0 = lo + hi + bv;
        upk(a1, lo, hi); float s1 = lo + hi + bv;
        size_t g0 = row0 + row;
        size_t b_ = g0 >> 10; int t_ = (int)(g0 & 1023);
        out[(b_ * Ss + (size_t)(Ss - 1 - t_)) * Ff + f] = s0;
        g0 += 1; b_ = g0 >> 10; t_ = (int)(g0 & 1023);
        out[(b_ * Ss + (size_t)(Ss - 1 - t_)) * Ff + f] = s1;
    }
}

// ------------------------- launch -------------------------
extern "C" void kernel_launch(void* const* d_in, const int* in_sizes, int n_in,
                              void* d_out, int out_size) {
    const float* x     = (const float*)d_in[0];
    const float* Wih_e = (const float*)d_in[1];
    const float* Whh_e = (const float*)d_in[2];
    const float* bih_e = (const float*)d_in[3];
    const float* bhh_e = (const float*)d_in[4];
    const float* Wih_d = (const float*)d_in[5];
    const float* Whh_d = (const float*)d_in[6];
    const float* bih_d = (const float*)d_in[7];
    const float* bhh_d = (const float*)d_in[8];
    const float* Wdn   = (const float*)d_in[9];
    const float* bdn   = (const float*)d_in[10];
    float* out = (float*)d_out;

    const int SM_X = 16 * 512 * 16 + 32 * 64 * 4;
    const int SM_O = 128 * Ll * 4;

    cudaFuncSetAttribute(xproj_kernel, cudaFuncAttributeMaxDynamicSharedMemorySize, SM_X);
    cudaFuncSetAttribute(rec_kernel<true>,  cudaFuncAttributeMaxDynamicSharedMemorySize, SMR);
    cudaFuncSetAttribute(rec_kernel<false>, cudaFuncAttributeMaxDynamicSharedMemorySize, SMR);
    cudaFuncSetAttribute(out_kernel, cudaFuncAttributeMaxDynamicSharedMemorySize, SM_O);

    setup_kernel<<<Gg, Ll>>>(Wih_d, Whh_d, bih_d, bhh_d, Wdn, bdn, bih_e, bhh_e);
    xproj_kernel<<<(Bb * Ss) / 32, 256, SM_X>>>(x, Wih_e);
    rec_kernel<true><<<Bb / 4, 512, SMR>>>(Whh_e);
    rec_kernel<false><<<Bb / 4, 512, SMR>>>(Whh_e);
    out_kernel<<<(Bb * Ss) / 128, 256, SM_O>>>(Wdn, bdn, out);
}

// round 15
// speedup vs baseline: 1.5379x; 1.1076x over previous
#include <cuda_runtime.h>
#include <cuda_bf16.h>
#include <cstdint>
#include <cstring>

typedef unsigned long long ull;

#define Bb 512
#define Ss 1024
#define Ff 64
#define Ll 128
#define Gg 512

// recurrent smem layout (bytes)
#define WB   0                    // W staging / W_lo: 512 rows x 272B
#define HHI  139264               // h_hi B tile: 8 rows x 272B
#define HLO  (139264 + 2176)      // h_lo B tile
#define GSB  (139264 + 4352)      // gs: 512 gates x 10 floats
#define SMR  (GSB + 512 * 10 * 4) // 164096

__device__ float g_gx[(size_t)Bb * Ss * Gg];
__device__ float g_hall[(size_t)Bb * Ss * Ll];
__device__ float g_weff[Gg * Ll];
__device__ float g_benc[Gg];
__device__ float g_beff[Gg];
__device__ float g_hn[Bb * Ll];
__device__ float g_cn[Bb * Ll];

__device__ __forceinline__ ull pk(float x, float y) {
    ull r; asm("mov.b64 %0, {%1, %2};" : "=l"(r) : "f"(x), "f"(y)); return r;
}
__device__ __forceinline__ void upk(ull v, float& x, float& y) {
    asm("mov.b64 {%0, %1}, %2;" : "=f"(x), "=f"(y) : "l"(v));
}
__device__ __forceinline__ void fma2(ull& d, ull a, ull b) {
    asm("fma.rn.f32x2 %0, %1, %2, %0;" : "+l"(d) : "l"(a), "l"(b));
}
__device__ __forceinline__ float ex2a(float x) {
    float r; asm("ex2.approx.f32 %0, %1;" : "=f"(r) : "f"(x)); return r;
}
__device__ __forceinline__ float rcpa(float x) {
    float r; asm("rcp.approx.f32 %0, %1;" : "=f"(r) : "f"(x)); return r;
}
__device__ __forceinline__ float fsig(float x) {
    return rcpa(1.0f + ex2a(-1.4426950408889634f * x));
}
__device__ __forceinline__ float ftanh(float x) {
    return fmaf(2.0f, rcpa(1.0f + ex2a(-2.8853900817779268f * x)), -1.0f);
}
__device__ __forceinline__ uint32_t smem_u32(const void* p) {
    uint32_t a;
    asm("{ .reg .u64 t; cvta.to.shared.u64 t, %1; cvt.u32.u64 %0, t; }" : "=r"(a) : "l"(p));
    return a;
}
__device__ __forceinline__ void ldsm4(uint32_t* f, uint32_t a) {
    asm volatile("ldmatrix.sync.aligned.m8n8.x4.shared.b16 {%0,%1,%2,%3}, [%4];"
                 : "=r"(f[0]), "=r"(f[1]), "=r"(f[2]), "=r"(f[3]) : "r"(a));
}
__device__ __forceinline__ void ldsm2(uint32_t* f, uint32_t a) {
    asm volatile("ldmatrix.sync.aligned.m8n8.x2.shared.b16 {%0,%1}, [%2];"
                 : "=r"(f[0]), "=r"(f[1]) : "r"(a));
}
__device__ __forceinline__ void mma_bf16(float* d, const uint32_t* a, const uint32_t* b) {
    asm volatile("mma.sync.aligned.m16n8k16.row.col.f32.bf16.bf16.f32 "
                 "{%0,%1,%2,%3},{%4,%5,%6,%7},{%8,%9},{%0,%1,%2,%3};"
                 : "+f"(d[0]), "+f"(d[1]), "+f"(d[2]), "+f"(d[3])
                 : "r"(a[0]), "r"(a[1]), "r"(a[2]), "r"(a[3]), "r"(b[0]), "r"(b[1]));
}
__device__ __forceinline__ uint32_t pack_bf16(float a, float b) {
    __nv_bfloat16 x = __float2bfloat16(a), y = __float2bfloat16(b);
    uint16_t u0, u1; memcpy(&u0, &x, 2); memcpy(&u1, &y, 2);
    return (uint32_t)u0 | ((uint32_t)u1 << 16);
}

// ------------------------- setup -------------------------
__global__ void setup_kernel(const float* __restrict__ Wih_d, const float* __restrict__ Whh_d,
                             const float* __restrict__ bih_d, const float* __restrict__ bhh_d,
                             const float* __restrict__ Wdn, const float* __restrict__ bdn,
                             const float* __restrict__ bih_e, const float* __restrict__ bhh_e) {
    int j = blockIdx.x, k = threadIdx.x;
    float s = 0.0f;
    for (int m = 0; m < Ff; m++) s += Wih_d[j * Ff + m] * Wdn[m * Ll + k];
    g_weff[j * Ll + k] = Whh_d[j * Ll + k] + s;
    if (k == 0) {
        float bs = bih_d[j] + bhh_d[j];
        for (int m = 0; m < Ff; m++) bs += Wih_d[j * Ff + m] * bdn[m];
        g_beff[j] = bs;
        g_benc[j] = bih_e[j] + bhh_e[j];
    }
}

// ------------------------- x-projection (fp32 scalar, proven) -------------------------
__global__ void __launch_bounds__(256, 1)
xproj_kernel(const float* __restrict__ x, const float* __restrict__ Wih) {
    extern __shared__ char smraw[];
    ulonglong2* Wsm = (ulonglong2*)smraw;
    float* xs = (float*)(smraw + 16 * 512 * 16);
    const int t_ = threadIdx.x;
    const int gA = t_, gB = t_ + 256;
    const float4* wa = (const float4*)(Wih + gA * Ff);
    const float4* wb = (const float4*)(Wih + gB * Ff);
#pragma unroll
    for (int kg = 0; kg < 16; kg++) {
        ((float4*)Wsm)[kg * 512 + gA] = wa[kg];
        ((float4*)Wsm)[kg * 512 + gB] = wb[kg];
    }
    const float bA = g_benc[gA], bB = g_benc[gB];
    const size_t row0 = (size_t)blockIdx.x * 32;
    ((float4*)xs)[t_] = ((const float4*)x)[row0 * 16 + t_];
    ((float4*)xs)[t_ + 256] = ((const float4*)x)[row0 * 16 + t_ + 256];
    __syncthreads();
    ull aA[32], aB[32];
#pragma unroll
    for (int r = 0; r < 32; r++) { aA[r] = 0ull; aB[r] = 0ull; }
#pragma unroll 4
    for (int kg = 0; kg < 16; kg++) {
        ulonglong2 wAv = Wsm[kg * 512 + gA];
        ulonglong2 wBv = Wsm[kg * 512 + gB];
#pragma unroll
        for (int r = 0; r < 32; r++) {
            ulonglong2 hh = *(const ulonglong2*)(xs + r * Ff + 4 * kg);
            fma2(aA[r], hh.x, wAv.x); fma2(aA[r], hh.y, wAv.y);
            fma2(aB[r], hh.x, wBv.x); fma2(aB[r], hh.y, wBv.y);
        }
    }
#pragma unroll
    for (int r = 0; r < 32; r++) {
        float lo, hi;
        upk(aA[r], lo, hi); g_gx[(row0 + r) * Gg + gA] = lo + hi + bA;
        upk(aB[r], lo, hi); g_gx[(row0 + r) * Gg + gB] = lo + hi + bB;
    }
}

// ------------------------- recurrent: mma.sync bf16 hi/lo (3 terms, split chains) -------------------------
// 128 CTAs x 512 threads; 4 real rows (cols 0-3), N padded to 8 with zero rows.
// Warp w: gates [32w, 32w+32) = 2 m-tiles. W_hi A-frags resident in regs;
// W_lo + h_lo streamed per step. D = Whi*hhi + Wlo*hhi + Whi*hlo over 3
// independent accumulator chains (8-deep each) for MMA latency hiding.
template <bool ENC>
__global__ void __launch_bounds__(512, 1)
rec_kernel(const float* __restrict__ Wsrc) {
    extern __shared__ char sm[];
    const uint32_t smb = smem_u32(sm);
    const int tid = threadIdx.x;
    const int lane = tid & 31, w = tid >> 5;
    const int l = tid & 127, r = tid >> 7;
    const int b0 = blockIdx.x * 4;
    const float* W = ENC ? Wsrc : (const float*)g_weff;

    // stage W_hi into WB (row stride 272B)
    for (int idx = tid; idx < 512 * 128; idx += 512) {
        int g = idx >> 7, k = idx & 127;
        *(__nv_bfloat16*)(sm + WB + g * 272 + 2 * k) = __float2bfloat16(W[g * 128 + k]);
    }
    __syncthreads();

    const uint32_t laneA = (uint32_t)((lane & 15) * 272 + (lane >> 4) * 16);
    const uint32_t laneB = (uint32_t)((lane & 7) * 272 + ((lane >> 3) & 1) * 16);

    // resident A_hi fragments
    uint32_t Ahi[2][8][4];
#pragma unroll
    for (int mt = 0; mt < 2; mt++) {
        uint32_t gb = smb + WB + (uint32_t)(w * 32 + mt * 16) * 272 + laneA;
#pragma unroll
        for (int kt = 0; kt < 8; kt++) ldsm4(Ahi[mt][kt], gb + kt * 32);
    }
    __syncthreads();

    // overwrite WB with W_lo residuals
    for (int idx = tid; idx < 512 * 128; idx += 512) {
        int g = idx >> 7, k = idx & 127;
        float wv = W[g * 128 + k];
        __nv_bfloat16 hh = __float2bfloat16(wv);
        *(__nv_bfloat16*)(sm + WB + g * 272 + 2 * k) =
            __float2bfloat16(wv - __bfloat162float(hh));
    }
    // zero h tiles (hi+lo = 4352B)
    for (int idx = tid; idx < 1088; idx += 512) ((uint32_t*)(sm + HHI))[idx] = 0u;

    float c, be0, be1, be2, be3, hn = 0.0f;
    if (ENC) {
        c = 0.0f;
    } else {
        c = g_cn[(b0 + r) * Ll + l];
        be0 = g_beff[l]; be1 = g_beff[128 + l]; be2 = g_beff[256 + l]; be3 = g_beff[384 + l];
    }
    __syncthreads();
    if (!ENC) {  // seed h from encoder
        float h0 = g_hn[(b0 + r) * Ll + l];
        float h1 = __shfl_down_sync(0xffffffffu, h0, 1);
        if (!(l & 1)) {
            __nv_bfloat16 a = __float2bfloat16(h0), b = __float2bfloat16(h1);
            *(uint32_t*)(sm + HHI + r * 272 + 2 * l) = pack_bf16(h0, h1);
            *(uint32_t*)(sm + HLO + r * 272 + 2 * l) =
                pack_bf16(h0 - __bfloat162float(a), h1 - __bfloat162float(b));
        }
        __syncthreads();
    }

    const uint32_t bhiB = smb + HHI + laneB;
    const uint32_t bloB = smb + HLO + laneB;
    float* gs = (float*)(sm + GSB);

    for (int t = 0; t < Ss; t++) {
        float gx0, gx1, gx2, gx3;
        if (ENC) {
            const float* p = g_gx + ((size_t)(b0 + r) * Ss + t) * Gg + l;
            gx0 = p[0]; gx1 = p[128]; gx2 = p[256]; gx3 = p[384];
        }
        // B_hi fragments resident for this step
        uint32_t Bh[8][2];
#pragma unroll
        for (int kt = 0; kt < 8; kt++) ldsm2(Bh[kt], bhiB + kt * 32);

        // GEMM: 3 terms, 3 independent accumulator chains per m-tile
#pragma unroll
        for (int mt = 0; mt < 2; mt++) {
            float DA[4] = {0.f, 0.f, 0.f, 0.f};
            float DB[4] = {0.f, 0.f, 0.f, 0.f};
            float DC[4] = {0.f, 0.f, 0.f, 0.f};
            uint32_t gb = smb + WB + (uint32_t)(w * 32 + mt * 16) * 272 + laneA;
#pragma unroll
            for (int kt = 0; kt < 8; kt++) {
                uint32_t Al[4], Bl[2];
                ldsm4(Al, gb + kt * 32);
                ldsm2(Bl, bloB + kt * 32);
                mma_bf16(DA, Ahi[mt][kt], Bh[kt]);   // hi*hi
                mma_bf16(DB, Al,          Bh[kt]);   // lo*hi
                mma_bf16(DC, Ahi[mt][kt], Bl);       // hi*lo
            }
            int g0 = w * 32 + mt * 16 + (lane >> 2);
            int cc = (lane & 3) * 2;
            *(float2*)(gs + g0 * 10 + cc) =
                make_float2(DA[0] + DB[0] + DC[0], DA[1] + DB[1] + DC[1]);
            *(float2*)(gs + (g0 + 8) * 10 + cc) =
                make_float2(DA[2] + DB[2] + DC[2], DA[3] + DB[3] + DC[3]);
        }
        __syncthreads();
        // cell update for (l, r)
        {
            float vi = gs[l * 10 + r]         + (ENC ? gx0 : be0);
            float vf = gs[(128 + l) * 10 + r] + (ENC ? gx1 : be1);
            float vg = gs[(256 + l) * 10 + r] + (ENC ? gx2 : be2);
            float vo = gs[(384 + l) * 10 + r] + (ENC ? gx3 : be3);
            c = fsig(vf) * c + fsig(vi) * ftanh(vg);
            hn = fsig(vo) * ftanh(c);
            if (!ENC) g_hall[((size_t)(b0 + r) * Ss + t) * Ll + l] = hn;
            float hn1 = __shfl_down_sync(0xffffffffu, hn, 1);
            if (!(l & 1)) {
                __nv_bfloat16 a = __float2bfloat16(hn), b = __float2bfloat16(hn1);
                *(uint32_t*)(sm + HHI + r * 272 + 2 * l) = pack_bf16(hn, hn1);
                *(uint32_t*)(sm + HLO + r * 272 + 2 * l) =
                    pack_bf16(hn - __bfloat162float(a), hn1 - __bfloat162float(b));
            }
        }
        __syncthreads();
    }
    if (ENC) {
        g_hn[(b0 + r) * Ll + l] = hn;
        g_cn[(b0 + r) * Ll + l] = c;
    }
}

// ------------------------- output GEMM + flip (proven) -------------------------
__global__ void __launch_bounds__(256, 1)
out_kernel(const float* __restrict__ Wdn, const float* __restrict__ bdn,
           float* __restrict__ out) {
    extern __shared__ float hsm[];
    const int tid = threadIdx.x;
    const size_t row0 = (size_t)blockIdx.x * 128;
    for (int i = tid; i < 128 * Ll / 4; i += 256)
        ((float4*)hsm)[i] = ((const float4*)g_hall)[row0 * (Ll / 4) + i];
    const int f = tid & 63, rgq = tid >> 6;
    ull Wd[64];
    const float4* wd = (const float4*)(Wdn + f * Ll);
#pragma unroll
    for (int q = 0; q < 32; q++) {
        float4 v = wd[q];
        Wd[2 * q] = pk(v.x, v.y); Wd[2 * q + 1] = pk(v.z, v.w);
    }
    const float bv = bdn[f];
    __syncthreads();
#pragma unroll 1
    for (int rr = 0; rr < 32; rr += 2) {
        int row = rgq * 32 + rr;
        ull a0 = 0, a1 = 0;
#pragma unroll
        for (int q = 0; q < 32; q++) {
            ulonglong2 h0 = *(const ulonglong2*)(hsm + row * Ll + 4 * q);
            ulonglong2 h1 = *(const ulonglong2*)(hsm + (row + 1) * Ll + 4 * q);
            fma2(a0, h0.x, Wd[2 * q]); fma2(a0, h0.y, Wd[2 * q + 1]);
            fma2(a1, h1.x, Wd[2 * q]); fma2(a1, h1.y, Wd[2 * q + 1]);
        }
        float lo, hi;
        upk(a0, lo, hi); float s0 = lo + hi + bv;
        upk(a1, lo, hi); float s1 = lo + hi + bv;
        size_t g0 = row0 + row;
        size_t b_ = g0 >> 10; int t_ = (int)(g0 & 1023);
        out[(b_ * Ss + (size_t)(Ss - 1 - t_)) * Ff + f] = s0;
        g0 += 1; b_ = g0 >> 10; t_ = (int)(g0 & 1023);
        out[(b_ * Ss + (size_t)(Ss - 1 - t_)) * Ff + f] = s1;
    }
}

// ------------------------- launch -------------------------
extern "C" void kernel_launch(void* const* d_in, const int* in_sizes, int n_in,
                              void* d_out, int out_size) {
    const float* x     = (const float*)d_in[0];
    const float* Wih_e = (const float*)d_in[1];
    const float* Whh_e = (const float*)d_in[2];
    const float* bih_e = (const float*)d_in[3];
    const float* bhh_e = (const float*)d_in[4];
    const float* Wih_d = (const float*)d_in[5];
    const float* Whh_d = (const float*)d_in[6];
    const float* bih_d = (const float*)d_in[7];
    const float* bhh_d = (const float*)d_in[8];
    const float* Wdn   = (const float*)d_in[9];
    const float* bdn   = (const float*)d_in[10];
    float* out = (float*)d_out;

    const int SM_X = 16 * 512 * 16 + 32 * 64 * 4;
    const int SM_O = 128 * Ll * 4;

    cudaFuncSetAttribute(xproj_kernel, cudaFuncAttributeMaxDynamicSharedMemorySize, SM_X);
    cudaFuncSetAttribute(rec_kernel<true>,  cudaFuncAttributeMaxDynamicSharedMemorySize, SMR);
    cudaFuncSetAttribute(rec_kernel<false>, cudaFuncAttributeMaxDynamicSharedMemorySize, SMR);
    cudaFuncSetAttribute(out_kernel, cudaFuncAttributeMaxDynamicSharedMemorySize, SM_O);

    setup_kernel<<<Gg, Ll>>>(Wih_d, Whh_d, bih_d, bhh_d, Wdn, bdn, bih_e, bhh_e);
    xproj_kernel<<<(Bb * Ss) / 32, 256, SM_X>>>(x, Wih_e);
    rec_kernel<true><<<Bb / 4, 512, SMR>>>(Whh_e);
    rec_kernel<false><<<Bb / 4, 512, SMR>>>(Whh_e);
    out_kernel<<<(Bb * Ss) / 128, 256, SM_O>>>(Wdn, bdn, out);
}